// round 13
// baseline (speedup 1.0000x reference)
#include <cuda_runtime.h>
#include <cuda_bf16.h>
#include <cuda_fp16.h>
#include <cstdint>

#define NODES   4096
#define GRAPHS  128
#define GSIZE   32
#define DIN     128
#define HK      128     // HEADS*KEY_SIZE
#define QKVN    384     // 3*HK
#define DOUT    4096

// bf16 hi/lo split operands for the precision-critical QKV GEMM
__device__ __align__(16) __nv_bfloat16 g_Whi[QKVN * DIN];    // [Wq|Wk|Wv]^T K-major
__device__ __align__(16) __nv_bfloat16 g_Wlo[QKVN * DIN];
__device__ __align__(16) float         g_bqkv[QKVN];
__device__ __align__(16) float         g_qkv[NODES * QKVN];  // q|k|v per node
// fp16 single-precision-pass operands for the output GEMM
__device__ __align__(16) __half        g_Af16[NODES * HK];
__device__ __align__(16) __half        g_Bf16[DOUT * HK];    // WoT K-major

__device__ __forceinline__ uint32_t smem_u32(const void* p) {
    uint32_t a;
    asm("{ .reg .u64 t; cvta.to.shared.u64 t, %1; cvt.u32.u64 %0, t; }"
        : "=r"(a) : "l"(p));
    return a;
}
__device__ __forceinline__ void ldsm_x4(uint32_t* d, uint32_t addr) {
    asm volatile("ldmatrix.sync.aligned.m8n8.x4.shared.b16 {%0,%1,%2,%3}, [%4];"
                 : "=r"(d[0]), "=r"(d[1]), "=r"(d[2]), "=r"(d[3]) : "r"(addr));
}
__device__ __forceinline__ void ldsm_x2(uint32_t* d, uint32_t addr) {
    asm volatile("ldmatrix.sync.aligned.m8n8.x2.shared.b16 {%0,%1}, [%2];"
                 : "=r"(d[0]), "=r"(d[1]) : "r"(addr));
}
__device__ __forceinline__ void mma16816(float* c, const uint32_t* a, const uint32_t* b) {
    asm volatile(
        "mma.sync.aligned.m16n8k16.row.col.f32.bf16.bf16.f32 "
        "{%0,%1,%2,%3}, {%4,%5,%6,%7}, {%8,%9}, {%0,%1,%2,%3};"
        : "+f"(c[0]), "+f"(c[1]), "+f"(c[2]), "+f"(c[3])
        : "r"(a[0]), "r"(a[1]), "r"(a[2]), "r"(a[3]), "r"(b[0]), "r"(b[1]));
}
__device__ __forceinline__ void mma16816h(float* c, const uint32_t* a, const uint32_t* b) {
    asm volatile(
        "mma.sync.aligned.m16n8k16.row.col.f32.f16.f16.f32 "
        "{%0,%1,%2,%3}, {%4,%5,%6,%7}, {%8,%9}, {%0,%1,%2,%3};"
        : "+f"(c[0]), "+f"(c[1]), "+f"(c[2]), "+f"(c[3])
        : "r"(a[0]), "r"(a[1]), "r"(a[2]), "r"(a[3]), "r"(b[0]), "r"(b[1]));
}
__device__ __forceinline__ void cp16(uint32_t smem_addr, const void* gptr) {
    asm volatile("cp.async.cg.shared.global [%0], [%1], 16;"
                 :: "r"(smem_addr), "l"(gptr) : "memory");
}
__device__ __forceinline__ void split_bf16(float x, __nv_bfloat16& h, __nv_bfloat16& l) {
    h = __float2bfloat16(x);
    l = __float2bfloat16(x - __bfloat162float(h));
}

// ---------------------------------------------------------------------------
// prep_all: weight conversions (no smem, dense occupancy).
// ---------------------------------------------------------------------------
__global__ __launch_bounds__(256) void prep_all(
    const float* __restrict__ Wq, const float* __restrict__ bq,
    const float* __restrict__ Wk, const float* __restrict__ bk,
    const float* __restrict__ Wv, const float* __restrict__ bv,
    const float* __restrict__ Wo)
{
    const int p   = blockIdx.x;
    const int tid = threadIdx.x;

    if (p < 256) {                      // Wo transpose -> fp16, n coalesced
        const int n  = (p & 15) * 256 + tid;
        const int kc = (p >> 4) * 8;
        __align__(16) __half hf[8];
        #pragma unroll
        for (int j = 0; j < 8; j++)
            hf[j] = __float2half(__ldg(&Wo[(size_t)(kc + j) * DOUT + n]));
        *(uint4*)&g_Bf16[(size_t)n * HK + kc] = *(uint4*)hf;
    } else {                            // Wq|Wk|Wv transpose + bias
        const int idx = (p - 256) * 256 + tid;   // [0, 6144)
        const int n   = idx >> 4;                // [0, 384)
        const int kc  = (idx & 15) * 8;
        const float* W = (n < HK) ? Wq : (n < 2 * HK) ? Wk : Wv;
        const float* b = (n < HK) ? bq : (n < 2 * HK) ? bk : bv;
        const int nl = n & (HK - 1);
        __align__(16) __nv_bfloat16 hb[8];
        __align__(16) __nv_bfloat16 lb[8];
        #pragma unroll
        for (int j = 0; j < 8; j++) {
            float x = __ldg(&W[(size_t)(kc + j) * HK + nl]);
            split_bf16(x, hb[j], lb[j]);
        }
        *(uint4*)&g_Whi[(size_t)n * DIN + kc] = *(uint4*)hb;
        *(uint4*)&g_Wlo[(size_t)n * DIN + kc] = *(uint4*)lb;
        if ((idx & 15) == 0) g_bqkv[n] = __ldg(&b[nl]);
    }
}

// ---------------------------------------------------------------------------
// qkv_gemm (bf16x3): C[128x64] = X @ Wqkv^T + b.  X converted during staging.
// 8 warps = 4(M)x2(N), warp tile 32x32. 256 threads.
// ---------------------------------------------------------------------------
#define BM 128
#define BN 64
#define ASTRIDE 136                     // 16b elems per smem row (odd 16B units)
#define ROWB    (ASTRIDE * 2)           // 272 bytes per smem row
#define TILE_A  (BM * ROWB)             // 34816 B
#define TILE_Bb (BN * ROWB)             // 17408 B
#define OFF_AHI 0
#define OFF_ALO (TILE_A)
#define OFF_BHI (2 * TILE_A)
#define OFF_BLO (2 * TILE_A + TILE_Bb)
#define GEMM_SMEM (2 * TILE_A + 2 * TILE_Bb)   // 104448 B

__global__ __launch_bounds__(256, 2) void qkv_gemm(const float* __restrict__ nodes)
{
    extern __shared__ char smem[];
    const uint32_t sbase = smem_u32(smem);
    const int tid  = threadIdx.x;
    const int wid  = tid >> 5;
    const int lane = tid & 31;
    const int bm0 = blockIdx.y * BM;
    const int bn0 = blockIdx.x * BN;

    // A staging with fused fp32->bf16 hi/lo conversion
    #pragma unroll
    for (int t = 0; t < (BM * 16) / 256; t++) {
        const int i  = tid + t * 256;
        const int r  = i >> 4;
        const int k8 = i & 15;
        const uint32_t so = (uint32_t)r * ROWB + (uint32_t)k8 * 16;
        const float4 v0 = *(const float4*)&nodes[(size_t)(bm0 + r) * DIN + k8 * 8];
        const float4 v1 = *(const float4*)&nodes[(size_t)(bm0 + r) * DIN + k8 * 8 + 4];
        const float xs[8] = {v0.x, v0.y, v0.z, v0.w, v1.x, v1.y, v1.z, v1.w};
        __align__(16) __nv_bfloat16 hb[8];
        __align__(16) __nv_bfloat16 lb[8];
        #pragma unroll
        for (int j = 0; j < 8; j++) split_bf16(xs[j], hb[j], lb[j]);
        *(uint4*)(smem + OFF_AHI + so) = *(uint4*)hb;
        *(uint4*)(smem + OFF_ALO + so) = *(uint4*)lb;
    }
    #pragma unroll
    for (int t = 0; t < (BN * 16) / 256; t++) {
        const int i  = tid + t * 256;
        const int r  = i >> 4;
        const int k8 = i & 15;
        const uint32_t so = (uint32_t)r * ROWB + (uint32_t)k8 * 16;
        const size_t gb = (size_t)(bn0 + r) * DIN + k8 * 8;
        *(uint4*)(smem + OFF_BHI + so) = *(const uint4*)&g_Whi[gb];
        *(uint4*)(smem + OFF_BLO + so) = *(const uint4*)&g_Wlo[gb];
    }
    __syncthreads();

    const int wm0 = (wid & 3) * 32;
    const int wn0 = (wid >> 2) * 32;

    float acc[2][4][4];
    #pragma unroll
    for (int mf = 0; mf < 2; mf++)
        #pragma unroll
        for (int nf = 0; nf < 4; nf++)
            #pragma unroll
            for (int r = 0; r < 4; r++) acc[mf][nf][r] = 0.f;

    const int a_row = lane & 15;
    const int a_col = (lane >> 4) * 8;
    const int b_row = lane & 7;
    const int b_col = ((lane >> 3) & 1) * 8;

    #pragma unroll
    for (int ks = 0; ks < 8; ks++) {
        const int k0 = ks * 16;
        uint32_t aHi[2][4], aLo[2][4], bHi[4][2], bLo[4][2];
        #pragma unroll
        for (int mf = 0; mf < 2; mf++) {
            const uint32_t off = (uint32_t)(wm0 + mf * 16 + a_row) * ROWB
                               + (uint32_t)(k0 + a_col) * 2;
            ldsm_x4(aHi[mf], sbase + OFF_AHI + off);
            ldsm_x4(aLo[mf], sbase + OFF_ALO + off);
        }
        #pragma unroll
        for (int nf = 0; nf < 4; nf++) {
            const uint32_t off = (uint32_t)(wn0 + nf * 8 + b_row) * ROWB
                               + (uint32_t)(k0 + b_col) * 2;
            ldsm_x2(bHi[nf], sbase + OFF_BHI + off);
            ldsm_x2(bLo[nf], sbase + OFF_BLO + off);
        }
        #pragma unroll
        for (int mf = 0; mf < 2; mf++)
            #pragma unroll
            for (int nf = 0; nf < 4; nf++) {
                mma16816(acc[mf][nf], aHi[mf], bHi[nf]);
                mma16816(acc[mf][nf], aHi[mf], bLo[nf]);
                mma16816(acc[mf][nf], aLo[mf], bHi[nf]);
            }
    }

    const int er = lane >> 2;
    const int ec = (lane & 3) * 2;
    #pragma unroll
    for (int nf = 0; nf < 4; nf++) {
        const int n = bn0 + wn0 + nf * 8 + ec;
        const float2 bv = *(const float2*)&g_bqkv[n];
        #pragma unroll
        for (int mf = 0; mf < 2; mf++) {
            const int m = bm0 + wm0 + mf * 16 + er;
            float2 v0, v1;
            v0.x = acc[mf][nf][0] + bv.x;
            v0.y = acc[mf][nf][1] + bv.y;
            v1.x = acc[mf][nf][2] + bv.x;
            v1.y = acc[mf][nf][3] + bv.y;
            *(float2*)&g_qkv[(size_t)m * QKVN + n]       = v0;
            *(float2*)&g_qkv[(size_t)(m + 8) * QKVN + n] = v1;
        }
    }
}

// ---------------------------------------------------------------------------
// Persistent fp16 out_gemm on grid 148, 256 threads, 8 warps = 4(M)x2(N),
// warp tile 32M x 64N. A FRAGMENTS CACHED IN REGISTERS (64 regs/thread) and
// reloaded only when the A tile switches (<=1x per CTA) — removes A ldmatrix
// traffic from the mainloop. B triple-buffered (mod-3, no trailing barrier).
// smem: 2 x A(34816) + 3 x B(34816) = 174080 B.
// ---------------------------------------------------------------------------
#define BN2     128
#define TILE_B2 (BN2 * ROWB)            // 34816 B
#define GRID_P  148
#define NTILES  1024                    // 32 x 32
#define PO_A    0                       // two A buffers
#define PO_B    (2 * TILE_A)            // three B buffers
#define P_SMEM  (2 * TILE_A + 3 * TILE_B2)   // 174080 B
#define PTHREADS 256

__device__ __forceinline__ void stage_A_f(uint32_t dst, int bm0, int tid) {
    #pragma unroll
    for (int t = 0; t < (BM * 16) / PTHREADS; t++) {
        const int i  = tid + t * PTHREADS;
        const int r  = i >> 4;
        const int k8 = i & 15;
        cp16(dst + (uint32_t)r * ROWB + (uint32_t)k8 * 16,
             &g_Af16[(size_t)(bm0 + r) * DIN + k8 * 8]);
    }
}
__device__ __forceinline__ void stage_B_f(uint32_t dst, int bn0, int tid) {
    #pragma unroll
    for (int t = 0; t < (BN2 * 16) / PTHREADS; t++) {
        const int i  = tid + t * PTHREADS;
        const int r  = i >> 4;
        const int k8 = i & 15;
        cp16(dst + (uint32_t)r * ROWB + (uint32_t)k8 * 16,
             &g_Bf16[(size_t)(bn0 + r) * DIN + k8 * 8]);
    }
}

__global__ __launch_bounds__(PTHREADS, 1) void out_gemm_f(
    const float* __restrict__ bo, float* __restrict__ out)
{
    extern __shared__ char smem[];
    const uint32_t sbase = smem_u32(smem);
    const int tid  = threadIdx.x;
    const int wid  = tid >> 5;
    const int lane = tid & 31;

    const int start = (blockIdx.x * NTILES) / GRID_P;
    const int end   = ((blockIdx.x + 1) * NTILES) / GRID_P;

    // prologue: stage A and B for first tile
    stage_A_f(sbase + PO_A, (start >> 5) * BM, tid);
    stage_B_f(sbase + PO_B, (start & 31) * BN2, tid);
    asm volatile("cp.async.commit_group;" ::: "memory");

    const int wm0 = (wid & 3) * 32;    // 4 M-warp rows over 128
    const int wn0 = (wid >> 2) * 64;   // 2 N-warp cols over 128
    const int a_row = lane & 15;
    const int a_col = (lane >> 4) * 8;
    const int b_row = ((lane >> 4) * 8) + (lane & 7);   // paired x4 (n16)
    const int b_col = ((lane >> 3) & 1) * 8;

    uint32_t aF[8][2][4];     // cached A fragments: [kstep][mf][reg]
    int loaded_am = -1;

    int abuf = 0;
    int bbuf = 0;
    int bnext = 1;
    for (int t = start; t < end; t++) {
        bool aswitch = false;
        if (t + 1 < end) {
            const int nm = (t + 1) >> 5;
            if (nm != (t >> 5)) {
                stage_A_f(sbase + PO_A + (abuf ^ 1) * TILE_A, nm * BM, tid);
                aswitch = true;
            }
            stage_B_f(sbase + PO_B + bnext * TILE_B2, ((t + 1) & 31) * BN2, tid);
            asm volatile("cp.async.commit_group;" ::: "memory");
            asm volatile("cp.async.wait_group 1;" ::: "memory");
        } else {
            asm volatile("cp.async.wait_group 0;" ::: "memory");
        }
        __syncthreads();   // current tile's data visible to all warps

        // (re)load A fragments into registers if the A tile changed
        const int am = t >> 5;
        if (am != loaded_am) {
            const uint32_t acur = sbase + PO_A + abuf * TILE_A;
            #pragma unroll
            for (int ks = 0; ks < 8; ks++) {
                #pragma unroll
                for (int mf = 0; mf < 2; mf++) {
                    const uint32_t off =
                        (uint32_t)(wm0 + mf * 16 + a_row) * ROWB
                        + (uint32_t)(ks * 16 + a_col) * 2;
                    ldsm_x4(aF[ks][mf], acur + off);
                }
            }
            loaded_am = am;
        }

        const uint32_t bcur = sbase + PO_B + bbuf * TILE_B2;

        float acc[2][8][4];
        #pragma unroll
        for (int mf = 0; mf < 2; mf++)
            #pragma unroll
            for (int nf = 0; nf < 8; nf++)
                #pragma unroll
                for (int r = 0; r < 4; r++) acc[mf][nf][r] = 0.f;

        #pragma unroll
        for (int ks = 0; ks < 8; ks++) {
            const int k0 = ks * 16;
            uint32_t bF[4][4];   // 4 paired loads, each = two n8 frags
            #pragma unroll
            for (int p = 0; p < 4; p++) {
                const uint32_t off = (uint32_t)(wn0 + p * 16 + b_row) * ROWB
                                   + (uint32_t)(k0 + b_col) * 2;
                ldsm_x4(bF[p], bcur + off);
            }
            #pragma unroll
            for (int mf = 0; mf < 2; mf++)
                #pragma unroll
                for (int nf = 0; nf < 8; nf++)
                    mma16816h(acc[mf][nf], aF[ks][mf], &bF[nf >> 1][(nf & 1) * 2]);
        }

        const int bm0 = (t >> 5) * BM;
        const int bn0 = (t & 31) * BN2;
        const int er = lane >> 2;
        const int ec = (lane & 3) * 2;
        #pragma unroll
        for (int nf = 0; nf < 8; nf++) {
            const int n = bn0 + wn0 + nf * 8 + ec;
            const float2 bv = *(const float2*)&bo[n];
            #pragma unroll
            for (int mf = 0; mf < 2; mf++) {
                const int m = bm0 + wm0 + mf * 16 + er;
                float2 v0, v1;
                v0.x = acc[mf][nf][0] + bv.x;
                v0.y = acc[mf][nf][1] + bv.y;
                v1.x = acc[mf][nf][2] + bv.x;
                v1.y = acc[mf][nf][3] + bv.y;
                *(float2*)&out[(size_t)m * DOUT + n]       = v0;
                *(float2*)&out[(size_t)(m + 8) * DOUT + n] = v1;
            }
        }
        // no trailing barrier: mod-3 B rotation keeps prefetch targets disjoint
        bbuf = bnext;
        bnext = (bnext == 2) ? 0 : bnext + 1;
        if (aswitch) abuf ^= 1;
    }
}

// ---------------------------------------------------------------------------
// attn2: per-graph softmax attention on precomputed q/k/v -> fp16 A.
// One CTA per graph (128 CTAs), 256 threads load, 128 compute.
// ---------------------------------------------------------------------------
__global__ __launch_bounds__(256, 1) void attn2()
{
    __shared__ float sm[GSIZE * QKVN];   // 49152 B
    const int g   = blockIdx.x;
    const int tid = threadIdx.x;

    {
        const float4* src = (const float4*)(g_qkv + (size_t)g * GSIZE * QKVN);
        float4* dst = (float4*)sm;
        #pragma unroll
        for (int i = tid; i < GSIZE * QKVN / 4; i += 256) dst[i] = src[i];
    }
    __syncthreads();

    if (tid < HK) {
        const int h = tid >> 5;
        const int i = tid & 31;
        const float* qrow = sm + i * QKVN + h * 32;
        float qv[32];
        #pragma unroll
        for (int k4 = 0; k4 < 8; k4++) {
            const float4 t = *(const float4*)&qrow[k4 * 4];
            qv[k4*4+0] = t.x; qv[k4*4+1] = t.y; qv[k4*4+2] = t.z; qv[k4*4+3] = t.w;
        }
        const float scale = 0.17677669529663687f;
        float lo[GSIZE];
        float mx = -1e30f;
        #pragma unroll 4
        for (int j = 0; j < GSIZE; j++) {
            const float* krow = sm + j * QKVN + HK + h * 32;
            float acc = 0.f;
            #pragma unroll
            for (int k4 = 0; k4 < 8; k4++) {
                const float4 t = *(const float4*)&krow[k4 * 4];
                acc += qv[k4*4+0] * t.x; acc += qv[k4*4+1] * t.y;
                acc += qv[k4*4+2] * t.z; acc += qv[k4*4+3] * t.w;
            }
            acc *= scale;
            lo[j] = acc;
            mx = fmaxf(mx, acc);
        }
        float s = 0.f;
        #pragma unroll
        for (int j = 0; j < GSIZE; j++) { lo[j] = __expf(lo[j] - mx); s += lo[j]; }
        const float inv = 1.f / s;

        float o[32];
        #pragma unroll
        for (int k = 0; k < 32; k++) o[k] = 0.f;
        #pragma unroll 4
        for (int j = 0; j < GSIZE; j++) {
            const float a = lo[j] * inv;
            const float* vrow = sm + j * QKVN + 2 * HK + h * 32;
            #pragma unroll
            for (int k4 = 0; k4 < 8; k4++) {
                const float4 t = *(const float4*)&vrow[k4 * 4];
                o[k4*4+0] += a * t.x; o[k4*4+1] += a * t.y;
                o[k4*4+2] += a * t.z; o[k4*4+3] += a * t.w;
            }
        }
        const size_t base = (size_t)(g * GSIZE + i) * HK + h * 32;
        #pragma unroll
        for (int c8 = 0; c8 < 4; c8++) {
            __align__(16) __half hf[8];
            #pragma unroll
            for (int j = 0; j < 8; j++) hf[j] = __float2half(o[c8 * 8 + j]);
            *(uint4*)&g_Af16[base + c8 * 8] = *(uint4*)hf;
        }
    }
}

// ---------------------------------------------------------------------------
// Inputs: nodes, n_node, Wq, bq, Wk, bk, Wv, bv, Wo, bo.
// ---------------------------------------------------------------------------
extern "C" void kernel_launch(void* const* d_in, const int* in_sizes, int n_in,
                              void* d_out, int out_size)
{
    const float* nodes = (const float*)d_in[0];
    const float* Wq    = (const float*)d_in[2];
    const float* bq    = (const float*)d_in[3];
    const float* Wk    = (const float*)d_in[4];
    const float* bk    = (const float*)d_in[5];
    const float* Wv    = (const float*)d_in[6];
    const float* bv    = (const float*)d_in[7];
    const float* Wo    = (const float*)d_in[8];
    const float* bo    = (const float*)d_in[9];
    float* out = (float*)d_out;

    prep_all<<<280, 256>>>(Wq, bq, Wk, bk, Wv, bv, Wo);

    cudaFuncSetAttribute(qkv_gemm, cudaFuncAttributeMaxDynamicSharedMemorySize,
                         GEMM_SMEM);
    qkv_gemm<<<dim3(QKVN / BN, NODES / BM), 256, GEMM_SMEM>>>(nodes);

    attn2<<<GRAPHS, 256>>>();

    cudaFuncSetAttribute(out_gemm_f, cudaFuncAttributeMaxDynamicSharedMemorySize,
                         P_SMEM);
    out_gemm_f<<<GRID_P, PTHREADS, P_SMEM>>>(bo, out);
}

// round 14
// speedup vs baseline: 1.0499x; 1.0499x over previous
#include <cuda_runtime.h>
#include <cuda_bf16.h>
#include <cuda_fp16.h>
#include <cstdint>

#define NODES   4096
#define GRAPHS  128
#define GSIZE   32
#define DIN     128
#define HK      128     // HEADS*KEY_SIZE
#define QKVN    384     // 3*HK
#define DOUT    4096

// bf16 hi/lo split operands for the precision-critical QKV GEMM
__device__ __align__(16) __nv_bfloat16 g_Whi[QKVN * DIN];    // [Wq|Wk|Wv]^T K-major
__device__ __align__(16) __nv_bfloat16 g_Wlo[QKVN * DIN];
__device__ __align__(16) float         g_bqkv[QKVN];
// fp16 single-precision-pass operands for the output GEMM
__device__ __align__(16) __half        g_Af16[NODES * HK];
__device__ __align__(16) __half        g_Bf16[DOUT * HK];    // WoT K-major

__device__ __forceinline__ uint32_t smem_u32(const void* p) {
    uint32_t a;
    asm("{ .reg .u64 t; cvta.to.shared.u64 t, %1; cvt.u32.u64 %0, t; }"
        : "=r"(a) : "l"(p));
    return a;
}
__device__ __forceinline__ void ldsm_x4(uint32_t* d, uint32_t addr) {
    asm volatile("ldmatrix.sync.aligned.m8n8.x4.shared.b16 {%0,%1,%2,%3}, [%4];"
                 : "=r"(d[0]), "=r"(d[1]), "=r"(d[2]), "=r"(d[3]) : "r"(addr));
}
__device__ __forceinline__ void ldsm_x2(uint32_t* d, uint32_t addr) {
    asm volatile("ldmatrix.sync.aligned.m8n8.x2.shared.b16 {%0,%1}, [%2];"
                 : "=r"(d[0]), "=r"(d[1]) : "r"(addr));
}
__device__ __forceinline__ void mma16816(float* c, const uint32_t* a, const uint32_t* b) {
    asm volatile(
        "mma.sync.aligned.m16n8k16.row.col.f32.bf16.bf16.f32 "
        "{%0,%1,%2,%3}, {%4,%5,%6,%7}, {%8,%9}, {%0,%1,%2,%3};"
        : "+f"(c[0]), "+f"(c[1]), "+f"(c[2]), "+f"(c[3])
        : "r"(a[0]), "r"(a[1]), "r"(a[2]), "r"(a[3]), "r"(b[0]), "r"(b[1]));
}
__device__ __forceinline__ void mma16816h(float* c, const uint32_t* a, const uint32_t* b) {
    asm volatile(
        "mma.sync.aligned.m16n8k16.row.col.f32.f16.f16.f32 "
        "{%0,%1,%2,%3}, {%4,%5,%6,%7}, {%8,%9}, {%0,%1,%2,%3};"
        : "+f"(c[0]), "+f"(c[1]), "+f"(c[2]), "+f"(c[3])
        : "r"(a[0]), "r"(a[1]), "r"(a[2]), "r"(a[3]), "r"(b[0]), "r"(b[1]));
}
__device__ __forceinline__ void cp16(uint32_t smem_addr, const void* gptr) {
    asm volatile("cp.async.cg.shared.global [%0], [%1], 16;"
                 :: "r"(smem_addr), "l"(gptr) : "memory");
}
__device__ __forceinline__ void split_bf16(float x, __nv_bfloat16& h, __nv_bfloat16& l) {
    h = __float2bfloat16(x);
    l = __float2bfloat16(x - __bfloat162float(h));
}

#define ASTRIDE 136                     // 16b elems per smem row (odd 16B units)
#define ROWB    (ASTRIDE * 2)           // 272 bytes per smem row

// ---------------------------------------------------------------------------
// prep_all: weight conversions (no smem, dense occupancy).
// ---------------------------------------------------------------------------
__global__ __launch_bounds__(256) void prep_all(
    const float* __restrict__ Wq, const float* __restrict__ bq,
    const float* __restrict__ Wk, const float* __restrict__ bk,
    const float* __restrict__ Wv, const float* __restrict__ bv,
    const float* __restrict__ Wo)
{
    const int p   = blockIdx.x;
    const int tid = threadIdx.x;

    if (p < 256) {                      // Wo transpose -> fp16, n coalesced
        const int n  = (p & 15) * 256 + tid;
        const int kc = (p >> 4) * 8;
        __align__(16) __half hf[8];
        #pragma unroll
        for (int j = 0; j < 8; j++)
            hf[j] = __float2half(__ldg(&Wo[(size_t)(kc + j) * DOUT + n]));
        *(uint4*)&g_Bf16[(size_t)n * HK + kc] = *(uint4*)hf;
    } else {                            // Wq|Wk|Wv transpose + bias
        const int idx = (p - 256) * 256 + tid;   // [0, 6144)
        const int n   = idx >> 4;                // [0, 384)
        const int kc  = (idx & 15) * 8;
        const float* W = (n < HK) ? Wq : (n < 2 * HK) ? Wk : Wv;
        const float* b = (n < HK) ? bq : (n < 2 * HK) ? bk : bv;
        const int nl = n & (HK - 1);
        __align__(16) __nv_bfloat16 hb[8];
        __align__(16) __nv_bfloat16 lb[8];
        #pragma unroll
        for (int j = 0; j < 8; j++) {
            float x = __ldg(&W[(size_t)(kc + j) * HK + nl]);
            split_bf16(x, hb[j], lb[j]);
        }
        *(uint4*)&g_Whi[(size_t)n * DIN + kc] = *(uint4*)hb;
        *(uint4*)&g_Wlo[(size_t)n * DIN + kc] = *(uint4*)lb;
        if ((idx & 15) == 0) g_bqkv[n] = __ldg(&b[nl]);
    }
}

// ---------------------------------------------------------------------------
// fused_qkv_attn: one CTA per graph (128 CTAs, 256 threads).
//  1) stage the graph's 32x128 node rows as bf16 hi/lo (fused convert)
//  2) bf16x3 MMA against Wqkv in 6 chunks of 64 N-cols (cp.async mod-3 bufs),
//     results (+bias) land as fp32 q|k|v in smem
//  3) per-(head,row) softmax attention straight from smem -> g_Af16
// smem: A 17408 + 3 x B 34816 + qkv 49152 = 171008 B.
// ---------------------------------------------------------------------------
#define FBM   32
#define FBN   64
#define FNC   (QKVN / FBN)              // 6 chunks
#define FA_HI 0
#define FA_LO (FBM * ROWB)              // 8704
#define FB    (2 * FBM * ROWB)          // 17408
#define FB_STR (2 * FBN * ROWB)         // 34816 per buffer (hi then lo)
#define FQKV  (FB + 3 * FB_STR)         // 121856
#define F_SMEM (FQKV + GSIZE * QKVN * 4)   // 171008

__global__ __launch_bounds__(256, 1) void fused_qkv_attn(
    const float* __restrict__ nodes)
{
    extern __shared__ char smem[];
    const uint32_t sbase = smem_u32(smem);
    float* qkv = (float*)(smem + FQKV);
    const int g    = blockIdx.x;
    const int tid  = threadIdx.x;
    const int wid  = tid >> 5;
    const int lane = tid & 31;

    // ---- stage A (32x128 nodes, fused fp32->bf16 hi/lo) ----
    #pragma unroll
    for (int t = 0; t < (FBM * 16) / 256; t++) {
        const int i  = tid + t * 256;
        const int r  = i >> 4;
        const int k8 = i & 15;
        const uint32_t so = (uint32_t)r * ROWB + (uint32_t)k8 * 16;
        const size_t gi = (size_t)(g * GSIZE + r) * DIN + k8 * 8;
        const float4 v0 = *(const float4*)&nodes[gi];
        const float4 v1 = *(const float4*)&nodes[gi + 4];
        const float xs[8] = {v0.x, v0.y, v0.z, v0.w, v1.x, v1.y, v1.z, v1.w};
        __align__(16) __nv_bfloat16 hb[8];
        __align__(16) __nv_bfloat16 lb[8];
        #pragma unroll
        for (int j = 0; j < 8; j++) split_bf16(xs[j], hb[j], lb[j]);
        *(uint4*)(smem + FA_HI + so) = *(uint4*)hb;
        *(uint4*)(smem + FA_LO + so) = *(uint4*)lb;
    }

    // ---- prologue: stage B chunk 0 (hi+lo) into buffer 0 ----
    {
        #pragma unroll
        for (int t = 0; t < (FBN * 16) / 256; t++) {
            const int i  = tid + t * 256;
            const int r  = i >> 4;
            const int k8 = i & 15;
            const uint32_t so = (uint32_t)r * ROWB + (uint32_t)k8 * 16;
            const size_t gb = (size_t)r * DIN + k8 * 8;
            cp16(sbase + FB + so,                 &g_Whi[gb]);
            cp16(sbase + FB + FBN * ROWB + so,    &g_Wlo[gb]);
        }
        asm volatile("cp.async.commit_group;" ::: "memory");
    }

    const int wn0   = wid * 8;          // each warp owns 8 N-cols of the chunk
    const int a_row = lane & 15;
    const int a_col = (lane >> 4) * 8;
    const int b_row = lane & 7;
    const int b_col = ((lane >> 3) & 1) * 8;

    int bbuf = 0, bnext = 1;
    for (int nc = 0; nc < FNC; nc++) {
        if (nc + 1 < FNC) {
            const uint32_t dst = sbase + FB + bnext * FB_STR;
            #pragma unroll
            for (int t = 0; t < (FBN * 16) / 256; t++) {
                const int i  = tid + t * 256;
                const int r  = i >> 4;
                const int k8 = i & 15;
                const uint32_t so = (uint32_t)r * ROWB + (uint32_t)k8 * 16;
                const size_t gb = (size_t)((nc + 1) * FBN + r) * DIN + k8 * 8;
                cp16(dst + so,              &g_Whi[gb]);
                cp16(dst + FBN * ROWB + so, &g_Wlo[gb]);
            }
            asm volatile("cp.async.commit_group;" ::: "memory");
            asm volatile("cp.async.wait_group 1;" ::: "memory");
        } else {
            asm volatile("cp.async.wait_group 0;" ::: "memory");
        }
        __syncthreads();

        const uint32_t bHiBase = sbase + FB + bbuf * FB_STR;
        const uint32_t bLoBase = bHiBase + FBN * ROWB;

        float acc[2][4];
        #pragma unroll
        for (int mf = 0; mf < 2; mf++)
            #pragma unroll
            for (int r = 0; r < 4; r++) acc[mf][r] = 0.f;

        #pragma unroll
        for (int ks = 0; ks < 8; ks++) {
            const int k0 = ks * 16;
            uint32_t aHi[2][4], aLo[2][4], bHi[2], bLo[2];
            #pragma unroll
            for (int mf = 0; mf < 2; mf++) {
                const uint32_t off = (uint32_t)(mf * 16 + a_row) * ROWB
                                   + (uint32_t)(k0 + a_col) * 2;
                ldsm_x4(aHi[mf], sbase + FA_HI + off);
                ldsm_x4(aLo[mf], sbase + FA_LO + off);
            }
            {
                const uint32_t off = (uint32_t)(wn0 + b_row) * ROWB
                                   + (uint32_t)(k0 + b_col) * 2;
                ldsm_x2(bHi, bHiBase + off);
                ldsm_x2(bLo, bLoBase + off);
            }
            #pragma unroll
            for (int mf = 0; mf < 2; mf++) {
                mma16816(acc[mf], aHi[mf], bHi);
                mma16816(acc[mf], aHi[mf], bLo);
                mma16816(acc[mf], aLo[mf], bHi);
            }
        }

        // write chunk results (+bias) to fp32 qkv smem
        const int er = lane >> 2;
        const int ec = (lane & 3) * 2;
        const int n  = nc * FBN + wn0 + ec;
        const float2 bv = *(const float2*)&g_bqkv[n];
        #pragma unroll
        for (int mf = 0; mf < 2; mf++) {
            const int m = mf * 16 + er;
            float2 v0, v1;
            v0.x = acc[mf][0] + bv.x;
            v0.y = acc[mf][1] + bv.y;
            v1.x = acc[mf][2] + bv.x;
            v1.y = acc[mf][3] + bv.y;
            *(float2*)&qkv[(size_t)m * QKVN + n]       = v0;
            *(float2*)&qkv[(size_t)(m + 8) * QKVN + n] = v1;
        }
        bbuf = bnext;
        bnext = (bnext == 2) ? 0 : bnext + 1;
    }
    __syncthreads();

    // ---- attention phase (threads 0..127), q/k/v fp32 in smem ----
    if (tid < HK) {
        const int h = tid >> 5;
        const int i = tid & 31;
        const float* qrow = qkv + i * QKVN + h * 32;
        float qv[32];
        #pragma unroll
        for (int k4 = 0; k4 < 8; k4++) {
            const float4 t = *(const float4*)&qrow[k4 * 4];
            qv[k4*4+0] = t.x; qv[k4*4+1] = t.y; qv[k4*4+2] = t.z; qv[k4*4+3] = t.w;
        }
        const float scale = 0.17677669529663687f;
        float lo[GSIZE];
        float mx = -1e30f;
        #pragma unroll 4
        for (int j = 0; j < GSIZE; j++) {
            const float* krow = qkv + j * QKVN + HK + h * 32;
            float acc = 0.f;
            #pragma unroll
            for (int k4 = 0; k4 < 8; k4++) {
                const float4 t = *(const float4*)&krow[k4 * 4];
                acc += qv[k4*4+0] * t.x; acc += qv[k4*4+1] * t.y;
                acc += qv[k4*4+2] * t.z; acc += qv[k4*4+3] * t.w;
            }
            acc *= scale;
            lo[j] = acc;
            mx = fmaxf(mx, acc);
        }
        float s = 0.f;
        #pragma unroll
        for (int j = 0; j < GSIZE; j++) { lo[j] = __expf(lo[j] - mx); s += lo[j]; }
        const float inv = 1.f / s;

        float o[32];
        #pragma unroll
        for (int k = 0; k < 32; k++) o[k] = 0.f;
        #pragma unroll 4
        for (int j = 0; j < GSIZE; j++) {
            const float a = lo[j] * inv;
            const float* vrow = qkv + j * QKVN + 2 * HK + h * 32;
            #pragma unroll
            for (int k4 = 0; k4 < 8; k4++) {
                const float4 t = *(const float4*)&vrow[k4 * 4];
                o[k4*4+0] += a * t.x; o[k4*4+1] += a * t.y;
                o[k4*4+2] += a * t.z; o[k4*4+3] += a * t.w;
            }
        }
        const size_t base = (size_t)(g * GSIZE + i) * HK + h * 32;
        #pragma unroll
        for (int c8 = 0; c8 < 4; c8++) {
            __align__(16) __half hf[8];
            #pragma unroll
            for (int j = 0; j < 8; j++) hf[j] = __float2half(o[c8 * 8 + j]);
            *(uint4*)&g_Af16[base + c8 * 8] = *(uint4*)hf;
        }
    }
}

// ---------------------------------------------------------------------------
// Persistent fp16 out_gemm on grid 148 (R12 proven version): 512 threads,
// 16 warps = 4M x 4N, warp tile 32x32. A double-buffered, B triple-buffered
// (mod-3, no trailing barrier). smem 174080 B.
// ---------------------------------------------------------------------------
#define BM 128
#define TILE_A  (BM * ROWB)             // 34816 B
#define BN2     128
#define TILE_B2 (BN2 * ROWB)            // 34816 B
#define GRID_P  148
#define NTILES  1024                    // 32 x 32
#define PO_A    0
#define PO_B    (2 * TILE_A)
#define P_SMEM  (2 * TILE_A + 3 * TILE_B2)   // 174080 B

__device__ __forceinline__ void stage_A_f(uint32_t dst, int bm0, int tid) {
    #pragma unroll
    for (int t = 0; t < (BM * 16) / 512; t++) {
        const int i  = tid + t * 512;
        const int r  = i >> 4;
        const int k8 = i & 15;
        cp16(dst + (uint32_t)r * ROWB + (uint32_t)k8 * 16,
             &g_Af16[(size_t)(bm0 + r) * DIN + k8 * 8]);
    }
}
__device__ __forceinline__ void stage_B_f(uint32_t dst, int bn0, int tid) {
    #pragma unroll
    for (int t = 0; t < (BN2 * 16) / 512; t++) {
        const int i  = tid + t * 512;
        const int r  = i >> 4;
        const int k8 = i & 15;
        cp16(dst + (uint32_t)r * ROWB + (uint32_t)k8 * 16,
             &g_Bf16[(size_t)(bn0 + r) * DIN + k8 * 8]);
    }
}

__global__ __launch_bounds__(512, 1) void out_gemm_f(
    const float* __restrict__ bo, float* __restrict__ out)
{
    extern __shared__ char smem[];
    const uint32_t sbase = smem_u32(smem);
    const int tid  = threadIdx.x;
    const int wid  = tid >> 5;
    const int lane = tid & 31;

    const int start = (blockIdx.x * NTILES) / GRID_P;
    const int end   = ((blockIdx.x + 1) * NTILES) / GRID_P;

    stage_A_f(sbase + PO_A, (start >> 5) * BM, tid);
    stage_B_f(sbase + PO_B, (start & 31) * BN2, tid);
    asm volatile("cp.async.commit_group;" ::: "memory");

    const int wm0 = (wid & 3) * 32;
    const int wn0 = (wid >> 2) * 32;
    const int a_row = lane & 15;
    const int a_col = (lane >> 4) * 8;
    const int b_row = lane & 7;
    const int b_col = ((lane >> 3) & 1) * 8;

    int abuf = 0;
    int bbuf = 0;
    int bnext = 1;
    for (int t = start; t < end; t++) {
        bool aswitch = false;
        if (t + 1 < end) {
            const int nm = (t + 1) >> 5;
            if (nm != (t >> 5)) {
                stage_A_f(sbase + PO_A + (abuf ^ 1) * TILE_A, nm * BM, tid);
                aswitch = true;
            }
            stage_B_f(sbase + PO_B + bnext * TILE_B2, ((t + 1) & 31) * BN2, tid);
            asm volatile("cp.async.commit_group;" ::: "memory");
            asm volatile("cp.async.wait_group 1;" ::: "memory");
        } else {
            asm volatile("cp.async.wait_group 0;" ::: "memory");
        }
        __syncthreads();

        const uint32_t acur = sbase + PO_A + abuf * TILE_A;
        const uint32_t bcur = sbase + PO_B + bbuf * TILE_B2;

        float acc[2][4][4];
        #pragma unroll
        for (int mf = 0; mf < 2; mf++)
            #pragma unroll
            for (int nf = 0; nf < 4; nf++)
                #pragma unroll
                for (int r = 0; r < 4; r++) acc[mf][nf][r] = 0.f;

        #pragma unroll
        for (int ks = 0; ks < 8; ks++) {
            const int k0 = ks * 16;
            uint32_t aF[2][4], bF[4][2];
            #pragma unroll
            for (int mf = 0; mf < 2; mf++) {
                const uint32_t off = (uint32_t)(wm0 + mf * 16 + a_row) * ROWB
                                   + (uint32_t)(k0 + a_col) * 2;
                ldsm_x4(aF[mf], acur + off);
            }
            #pragma unroll
            for (int nf = 0; nf < 4; nf++) {
                const uint32_t off = (uint32_t)(wn0 + nf * 8 + b_row) * ROWB
                                   + (uint32_t)(k0 + b_col) * 2;
                ldsm_x2(bF[nf], bcur + off);
            }
            #pragma unroll
            for (int mf = 0; mf < 2; mf++)
                #pragma unroll
                for (int nf = 0; nf < 4; nf++)
                    mma16816h(acc[mf][nf], aF[mf], bF[nf]);
        }

        const int bm0 = (t >> 5) * BM;
        const int bn0 = (t & 31) * BN2;
        const int er = lane >> 2;
        const int ec = (lane & 3) * 2;
        #pragma unroll
        for (int nf = 0; nf < 4; nf++) {
            const int n = bn0 + wn0 + nf * 8 + ec;
            const float2 bv = *(const float2*)&bo[n];
            #pragma unroll
            for (int mf = 0; mf < 2; mf++) {
                const int m = bm0 + wm0 + mf * 16 + er;
                float2 v0, v1;
                v0.x = acc[mf][nf][0] + bv.x;
                v0.y = acc[mf][nf][1] + bv.y;
                v1.x = acc[mf][nf][2] + bv.x;
                v1.y = acc[mf][nf][3] + bv.y;
                *(float2*)&out[(size_t)m * DOUT + n]       = v0;
                *(float2*)&out[(size_t)(m + 8) * DOUT + n] = v1;
            }
        }
        bbuf = bnext;
        bnext = (bnext == 2) ? 0 : bnext + 1;
        if (aswitch) abuf ^= 1;
    }
}

// ---------------------------------------------------------------------------
// Inputs: nodes, n_node, Wq, bq, Wk, bk, Wv, bv, Wo, bo.
// ---------------------------------------------------------------------------
extern "C" void kernel_launch(void* const* d_in, const int* in_sizes, int n_in,
                              void* d_out, int out_size)
{
    const float* nodes = (const float*)d_in[0];
    const float* Wq    = (const float*)d_in[2];
    const float* bq    = (const float*)d_in[3];
    const float* Wk    = (const float*)d_in[4];
    const float* bk    = (const float*)d_in[5];
    const float* Wv    = (const float*)d_in[6];
    const float* bv    = (const float*)d_in[7];
    const float* Wo    = (const float*)d_in[8];
    const float* bo    = (const float*)d_in[9];
    float* out = (float*)d_out;

    prep_all<<<280, 256>>>(Wq, bq, Wk, bk, Wv, bv, Wo);

    cudaFuncSetAttribute(fused_qkv_attn,
                         cudaFuncAttributeMaxDynamicSharedMemorySize, F_SMEM);
    fused_qkv_attn<<<GRAPHS, 256, F_SMEM>>>(nodes);

    cudaFuncSetAttribute(out_gemm_f, cudaFuncAttributeMaxDynamicSharedMemorySize,
                         P_SMEM);
    out_gemm_f<<<GRID_P, 512, P_SMEM>>>(bo, out);
}